// round 16
// baseline (speedup 1.0000x reference)
#include <cuda_runtime.h>
#include <math.h>

// HierarchicalAttention — GB300 sm_103a, R14
// 5 launches: front(proj + src-half GEMM [K-split x16], detect)
//          -> align(dots + both softmaxes + zero g_c)
//          -> context(sparse weighted sum, atomics into g_c)
//          -> gemm_c(c-half GEMM, K-split x16, single-tile blocks)
//          -> tanh(sum 32 partials + tanh)
//
// Output: attn_h (B,D) | align_vectors (B,S) | ac (B,C-1) | au (B,S)

#define B_    32
#define D_    1024
#define UD_   256
#define ENT_  32
#define NENT_ 64
#define S_    2048
#define C_    65
#define KSPL  4      // K-splits for proj GEMM (summed in k_align)
#define KSW   16     // K-splits for the two W_out half GEMMs (one tile/block)

#define OUT_ATTN 0
#define OUT_AV   (B_*D_)
#define OUT_AC   (OUT_AV + B_*S_)
#define OUT_AU   (OUT_AC + B_*(C_-1))

// ---- static scratch ----
__device__ float g_qp[KSPL][B_*(UD_+D_)];  // proj partials: [m*1280 + n]
__device__ float g_hs[KSW][B_*D_];         // src-half output-GEMM partials (2MB)
__device__ float g_hc[KSW][B_*D_];         // c-half output-GEMM partials  (2MB)
__device__ float g_acs[B_*NENT_];          // chunk softmax (chunks 1..64)
__device__ float g_c[B_*D_];               // atomically accumulated context
__device__ int   g_mode_ll;                // 0=int32, 1=float32, 2=uint8
__device__ int   g_mode_hl;

__device__ __forceinline__ bool read_mask(const void* p, int idx, int mode) {
    if (mode == 0) return ((const int*)p)[idx] != 0;
    if (mode == 1) return ((const float*)p)[idx] != 0.0f;
    return ((const unsigned char*)p)[idx] != 0;
}
__device__ __forceinline__ float warp_sum(float v) {
    #pragma unroll
    for (int o = 16; o; o >>= 1) v += __shfl_xor_sync(0xFFFFFFFFu, v, o);
    return v;
}
__device__ __forceinline__ float warp_max(float v) {
    #pragma unroll
    for (int o = 16; o; o >>= 1) v = fmaxf(v, __shfl_xor_sync(0xFFFFFFFFu, v, o));
    return v;
}

// ---------------------------------------------------------------------------
// GEMM primitive: 32(M)x32(N) output tile over `ntiles` K-tiles of 64.
// 128 threads: lane = m, warp owns 8 n-columns (As bytes amortized 8x).
// With ntiles==1 (the K-split-16 path) there is NO serial K-chain: all 8
// global loads per thread are independent -> latency covered by grid size.
// ---------------------------------------------------------------------------
__device__ __forceinline__ void gemm_tile(const float* __restrict__ A, int lda,
                                          const float* __restrict__ Bn, int ldb,
                                          int k0, int ntiles,
                                          float* __restrict__ dst, int ldd) {
    __shared__ __align__(16) float As[32][68];
    __shared__ __align__(16) float Bs[32][68];
    int t = threadIdx.x, lane = t & 31, wid = t >> 5;
    float acc[8];
    #pragma unroll
    for (int j = 0; j < 8; j++) acc[j] = 0.f;

    for (int kt = 0; kt < ntiles; kt++) {
        int kk0 = k0 + kt * 64;
        #pragma unroll
        for (int i = 0; i < 4; i++) {
            int idx = t + i * 128;              // 512 float4 each
            int r = idx >> 4, c = (idx & 15) * 4;
            *(float4*)&As[r][c] = *(const float4*)&A [(size_t)r * lda + kk0 + c];
            *(float4*)&Bs[r][c] = *(const float4*)&Bn[(size_t)r * ldb + kk0 + c];
        }
        __syncthreads();
        #pragma unroll
        for (int i = 0; i < 16; i++) {
            float4 a = *(const float4*)&As[lane][i * 4];
            #pragma unroll
            for (int j = 0; j < 8; j++) {
                float4 b = *(const float4*)&Bs[wid * 8 + j][i * 4];
                acc[j] += a.x*b.x + a.y*b.y + a.z*b.z + a.w*b.w;
            }
        }
        __syncthreads();
    }
    #pragma unroll
    for (int j = 0; j < 8; j++)
        dst[lane * ldd + wid * 8 + j] = acc[j];
}

// ---------------------------------------------------------------------------
// K1 front:
//  [0,160):   proj GEMM (40 n-groups x 4 K-splits, 4 tiles each) -> g_qp[ks]
//  [160,672): src-half of output GEMM (32 n-groups x 16 K-splits, ONE tile
//             per block) -> g_hs[ks]
//  [672,674): mask dtype detection
// ---------------------------------------------------------------------------
__global__ void k_front(const float* __restrict__ src,
                        const float* __restrict__ Wu,
                        const float* __restrict__ Wc,
                        const float* __restrict__ Wo,
                        const unsigned int* __restrict__ llm,
                        const unsigned int* __restrict__ hlm) {
    int bx = blockIdx.x, t = threadIdx.x;
    if (bx >= 672) {
        // int32 words are {0,1}; f32 words are {0,0x3F800000}; packed uint8
        // words hit neither set (random 0/1 data).
        __shared__ int s_ni, s_nf;
        if (t == 0) { s_ni = 0; s_nf = 0; }
        __syncthreads();
        int which = bx - 672;
        const unsigned int* p = which ? hlm : llm;
        int n = which ? (B_*C_ / 4) : (NENT_*B_*ENT_ / 4);
        int ni = 0, nf = 0;
        for (int i = t; i < n; i += blockDim.x) {
            unsigned int w = p[i];
            if (w > 1u) ni = 1;
            if (w != 0u && w != 0x3F800000u) nf = 1;
        }
        if (ni) atomicOr(&s_ni, 1);
        if (nf) atomicOr(&s_nf, 1);
        __syncthreads();
        if (t == 0) {
            int mode = (!s_ni) ? 0 : ((!s_nf) ? 1 : 2);
            if (which) g_mode_hl = mode; else g_mode_ll = mode;
        }
        return;
    }
    if (bx < 160) {
        int g = bx >> 2, ks = bx & 3;
        int n0 = g * 32;
        const float* Bn;
        if (n0 < 256) Bn = Wu + (size_t)n0 * D_;
        else          Bn = Wc + (size_t)(n0 - 256) * D_;
        gemm_tile(src, D_, Bn, D_, ks * 256, 4, &g_qp[ks][n0], UD_ + D_);
    } else {
        int h = bx - 160;
        int g = h >> 4, ks = h & 15;          // 32 n-groups x 16 K-splits
        int n0 = g * 32;
        gemm_tile(src, D_, Wo + (size_t)n0 * (2*D_) + D_, 2*D_,
                  ks * 64, 1, &g_hs[ks][n0], D_);
    }
}

// ---------------------------------------------------------------------------
// K2 align — alignment dots + both softmaxes; first 256 unit blocks also
// zero g_c for K3's atomics.
// ---------------------------------------------------------------------------
__global__ void k_align(const float* __restrict__ pe,
                        const float* __restrict__ hl,
                        const void* llm, const void* hlm,
                        float* __restrict__ out) {
    int t = threadIdx.x, w = t >> 5, lane = t & 31;
    if (blockIdx.x < 2048) {
        int b = blockIdx.x & 31, e = blockIdx.x >> 5;
        if (blockIdx.x < 256 && t < 32)
            ((float4*)g_c)[blockIdx.x * 32 + t] = make_float4(0.f, 0.f, 0.f, 0.f);
        __shared__ __align__(16) float sq[UD_];
        __shared__ float s_val[ENT_];
        __shared__ unsigned s_bm;
        if (t < 64) {
            float4 q = make_float4(0.f, 0.f, 0.f, 0.f);
            #pragma unroll
            for (int ks = 0; ks < KSPL; ks++) {
                float4 p = ((const float4*)g_qp[ks])[b * ((UD_+D_)/4) + t];
                q.x += p.x; q.y += p.y; q.z += p.z; q.w += p.w;
            }
            ((float4*)sq)[t] = q;
        }
        if (w == 0) {
            bool mk = read_mask(llm, e * (B_*ENT_) + b * ENT_ + lane, g_mode_ll);
            unsigned bm = __ballot_sync(0xFFFFFFFFu, mk);
            if (lane == 0) s_bm = bm;
        }
        __syncthreads();
        unsigned bm = s_bm;
        float4 q0 = ((const float4*)sq)[lane];
        float4 q1 = ((const float4*)sq)[lane + 32];
        const float4* peb = (const float4*)pe + (size_t)b * (UD_/4) + lane;
        const size_t RS = (size_t)B_ * UD_ / 4;
        int s0 = e * ENT_ + w * 4;
        float4 v[4][2];
        #pragma unroll
        for (int r = 0; r < 4; r++) {
            if (!((bm >> (w*4 + r)) & 1u)) {
                const float4* p = peb + (size_t)(s0 + r) * RS;
                v[r][0] = p[0];
                v[r][1] = p[32];
            }
        }
        #pragma unroll
        for (int r = 0; r < 4; r++) {
            if (!((bm >> (w*4 + r)) & 1u)) {
                float acc = v[r][0].x*q0.x + v[r][0].y*q0.y + v[r][0].z*q0.z + v[r][0].w*q0.w
                          + v[r][1].x*q1.x + v[r][1].y*q1.y + v[r][1].z*q1.z + v[r][1].w*q1.w;
                acc = warp_sum(acc);
                if (lane == 0) s_val[w*4 + r] = acc;
            } else if (lane == 0) {
                s_val[w*4 + r] = -INFINITY;
            }
        }
        __syncthreads();
        if (w == 0) {
            float vv = s_val[lane];
            float mx = warp_max(vv);
            float au;
            if (mx == -INFINITY) {
                au = 0.f;                       // all-masked entity
            } else {
                float ex = (vv == -INFINITY) ? 0.f : __expf(vv - mx);
                float sm = warp_sum(ex);
                au = ex / sm;
            }
            out[OUT_AU + b * S_ + e * ENT_ + lane] = au;
        }
    } else {
        int b = blockIdx.x - 2048;
        __shared__ __align__(16) float sqc[D_];
        __shared__ float s_sc[C_];
        {
            float4 q = make_float4(0.f, 0.f, 0.f, 0.f);
            #pragma unroll
            for (int ks = 0; ks < KSPL; ks++) {
                float4 p = ((const float4*)g_qp[ks])[b * ((UD_+D_)/4) + 64 + t];
                q.x += p.x; q.y += p.y; q.z += p.z; q.w += p.w;
            }
            ((float4*)sqc)[t] = q;
        }
        __syncthreads();
        int mhl = g_mode_hl;
        for (int c = w; c < C_; c += 8) {
            if (read_mask(hlm, b * C_ + c, mhl)) {
                if (lane == 0) s_sc[c] = -INFINITY;
                continue;
            }
            const float4* p = (const float4*)hl + ((size_t)c * B_ + b) * (D_/4);
            float acc = 0.f;
            #pragma unroll
            for (int it = 0; it < 8; it++) {
                float4 x = p[lane + it*32];
                float4 y = ((const float4*)sqc)[lane + it*32];
                acc += x.x*y.x + x.y*y.y + x.z*y.z + x.w*y.w;
            }
            acc = warp_sum(acc);
            if (lane == 0) s_sc[c] = acc;
        }
        __syncthreads();
        if (t == 0) {
            float mx = -INFINITY;
            for (int c = 0; c < C_; c++) mx = fmaxf(mx, s_sc[c]);
            float sum = 0.f;
            for (int c = 0; c < C_; c++) {
                float e = (s_sc[c] == -INFINITY) ? 0.f : __expf(s_sc[c] - mx);
                s_sc[c] = e; sum += e;
            }
            float inv = 1.f / sum;
            for (int c = 1; c < C_; c++) {
                float vv = s_sc[c] * inv;
                g_acs[b * NENT_ + (c-1)] = vv;
                out[OUT_AC + b * (C_-1) + (c-1)] = vv;
            }
        }
    }
}

// ---------------------------------------------------------------------------
// K3 context. Block = (entity e, batch b, D-half); computes av = au*ac[e]
// (writes av output), ballot-compacts nonzero weights, up to 16 LDG.128 in
// flight before FMAs, RED.ADD.F32 into g_c. ~75% of rows exactly zero ->
// never loaded; cnt==0 blocks exit with zero ll traffic.
// ---------------------------------------------------------------------------
__global__ void k_context(const float* __restrict__ ll, float* __restrict__ out) {
    int e = blockIdx.x, b = blockIdx.y, half = blockIdx.z, t = threadIdx.x;
    __shared__ float sw[ENT_];
    __shared__ int   sidx[ENT_];
    __shared__ int   scnt;
    float ac = g_acs[b * NENT_ + e];
    if (t < 32) {
        float au = out[OUT_AU + b * S_ + e * ENT_ + t];
        float av = au * ac;
        if (half == 0) out[OUT_AV + b * S_ + e * ENT_ + t] = av;
        unsigned m = __ballot_sync(0xFFFFFFFFu, av != 0.f);
        int pos = __popc(m & ((1u << t) - 1u));
        if (av != 0.f) { sw[pos] = av; sidx[pos] = t; }
        if (t == 0) scnt = __popc(m);
    }
    __syncthreads();
    int cnt = scnt;
    if (cnt == 0) return;
    float4 acc = make_float4(0.f, 0.f, 0.f, 0.f);
    const float4* base = (const float4*)ll + (size_t)b * (D_/4) + half * 128 + t;
    const size_t RS = (size_t)B_ * D_ / 4;
    int k = 0;
    for (; k + 16 <= cnt; k += 16) {
        float4 v[16];
        #pragma unroll
        for (int u = 0; u < 16; u++)
            v[u] = base[(size_t)(e * ENT_ + sidx[k + u]) * RS];
        #pragma unroll
        for (int u = 0; u < 16; u++) {
            float w = sw[k + u];
            acc.x += w * v[u].x; acc.y += w * v[u].y;
            acc.z += w * v[u].z; acc.w += w * v[u].w;
        }
    }
    for (; k + 8 <= cnt; k += 8) {
        float4 v[8];
        #pragma unroll
        for (int u = 0; u < 8; u++)
            v[u] = base[(size_t)(e * ENT_ + sidx[k + u]) * RS];
        #pragma unroll
        for (int u = 0; u < 8; u++) {
            float w = sw[k + u];
            acc.x += w * v[u].x; acc.y += w * v[u].y;
            acc.z += w * v[u].z; acc.w += w * v[u].w;
        }
    }
    for (; k + 4 <= cnt; k += 4) {
        float4 v[4];
        #pragma unroll
        for (int u = 0; u < 4; u++)
            v[u] = base[(size_t)(e * ENT_ + sidx[k + u]) * RS];
        #pragma unroll
        for (int u = 0; u < 4; u++) {
            float w = sw[k + u];
            acc.x += w * v[u].x; acc.y += w * v[u].y;
            acc.z += w * v[u].z; acc.w += w * v[u].w;
        }
    }
    for (; k < cnt; k++) {
        float4 v = base[(size_t)(e * ENT_ + sidx[k]) * RS];
        float w = sw[k];
        acc.x += w * v.x; acc.y += w * v.y; acc.z += w * v.z; acc.w += w * v.w;
    }
    float* dst = &g_c[b * D_ + half * 512 + t * 4];
    atomicAdd(dst + 0, acc.x);
    atomicAdd(dst + 1, acc.y);
    atomicAdd(dst + 2, acc.z);
    atomicAdd(dst + 3, acc.w);
}

// ---------------------------------------------------------------------------
// K4: c-half of the output GEMM. 32 n-groups x 16 K-splits = 512 blocks,
// ONE 32x32x64 tile per block: zero serial K-chain, all loads independent.
// ---------------------------------------------------------------------------
__global__ void k_gemm_c(const float* __restrict__ Wo) {
    int g = blockIdx.x >> 4, ks = blockIdx.x & 15;
    int n0 = g * 32;
    gemm_tile(g_c, D_, Wo + (size_t)n0 * (2*D_), 2*D_,
              ks * 64, 1, &g_hc[ks][n0], D_);
}

// ---------------------------------------------------------------------------
// K5: attn_h = tanh(sum of all 32 partials).
// ---------------------------------------------------------------------------
__global__ void k_tanh(float* __restrict__ out) {
    int i = blockIdx.x * 256 + threadIdx.x;   // float4 index, 8192 total
    float4 s = make_float4(0.f, 0.f, 0.f, 0.f);
    #pragma unroll
    for (int ks = 0; ks < KSW; ks++) {
        float4 a = ((const float4*)g_hc[ks])[i];
        float4 b = ((const float4*)g_hs[ks])[i];
        s.x += a.x + b.x; s.y += a.y + b.y;
        s.z += a.z + b.z; s.w += a.w + b.w;
    }
    float4 r;
    r.x = tanhf(s.x); r.y = tanhf(s.y); r.z = tanhf(s.z); r.w = tanhf(s.w);
    ((float4*)(out + OUT_ATTN))[i] = r;
}

// ---------------------------------------------------------------------------
extern "C" void kernel_launch(void* const* d_in, const int* in_sizes, int n_in,
                              void* d_out, int out_size) {
    const float* src = (const float*)d_in[0];
    const float* hl  = (const float*)d_in[1];
    const float* pe  = (const float*)d_in[2];
    const float* ll  = (const float*)d_in[3];
    const void*  llm = d_in[4];
    const void*  hlm = d_in[5];
    const float* Wu  = (const float*)d_in[6];
    const float* Wc  = (const float*)d_in[7];
    const float* Wo  = (const float*)d_in[8];
    float* out = (float*)d_out;

    k_front<<<674, 128>>>(src, Wu, Wc, Wo,
                          (const unsigned int*)llm, (const unsigned int*)hlm);
    k_align<<<2048 + 32, 256>>>(pe, hl, llm, hlm, out);
    k_context<<<dim3(NENT_, B_, 2), 128>>>(ll, out);
    k_gemm_c<<<512, 128>>>(Wo);
    k_tanh<<<32, 256>>>(out);
}

// round 17
// speedup vs baseline: 1.0609x; 1.0609x over previous
#include <cuda_runtime.h>
#include <math.h>

// HierarchicalAttention — GB300 sm_103a, R17
// 4 launches: front(proj + src-half GEMM + detect + counter reset)
//          -> align(dots [compacted, MLP8] + both softmaxes + zero g_c)
//          -> context(sparse weighted sum, atomics into g_c)
//          -> gemm_c(c-half GEMM + fused partial-sum + tanh epilogue)
//
// Output: attn_h (B,D) | align_vectors (B,S) | ac (B,C-1) | au (B,S)

#define B_    32
#define D_    1024
#define UD_   256
#define ENT_  32
#define NENT_ 64
#define S_    2048
#define C_    65
#define KSPL  4      // K-splits for proj GEMM (summed in k_align)
#define KSW   16     // K-splits for the two W_out half GEMMs (one tile/block)

#define OUT_ATTN 0
#define OUT_AV   (B_*D_)
#define OUT_AC   (OUT_AV + B_*S_)
#define OUT_AU   (OUT_AC + B_*(C_-1))

// ---- static scratch ----
__device__ float g_qp[KSPL][B_*(UD_+D_)];  // proj partials: [m*1280 + n]
__device__ float g_hs[KSW][B_*D_];         // src-half output-GEMM partials
__device__ float g_hc[KSW][B_*D_];         // c-half output-GEMM partials
__device__ float g_acs[B_*NENT_];          // chunk softmax (chunks 1..64)
__device__ float g_c[B_*D_];               // atomically accumulated context
__device__ int   g_cnt[32];                // per-n-group completion counters
__device__ int   g_mode_ll;                // 0=int32, 1=float32, 2=uint8
__device__ int   g_mode_hl;

__device__ __forceinline__ bool read_mask(const void* p, int idx, int mode) {
    if (mode == 0) return ((const int*)p)[idx] != 0;
    if (mode == 1) return ((const float*)p)[idx] != 0.0f;
    return ((const unsigned char*)p)[idx] != 0;
}
__device__ __forceinline__ float warp_sum(float v) {
    #pragma unroll
    for (int o = 16; o; o >>= 1) v += __shfl_xor_sync(0xFFFFFFFFu, v, o);
    return v;
}
__device__ __forceinline__ float warp_max(float v) {
    #pragma unroll
    for (int o = 16; o; o >>= 1) v = fmaxf(v, __shfl_xor_sync(0xFFFFFFFFu, v, o));
    return v;
}

// ---------------------------------------------------------------------------
// GEMM primitive v2: 32(M)x32(N) tile, `ntiles` K-tiles of 64, 128 threads.
// ROLE SWAP vs R12-R14: lane = n-column, warp owns 8 m-rows. As is now the
// broadcast operand; Bs[lane] is conflict-free (stride 68 words, 4Δ mod 32
// nonzero within an LDS.128 phase). Stores are dst[m*ldd + lane]: one 128B
// coalesced line per warp-store instead of 32 scattered lines — kills the
// 8x write amplification that kept every GEMM kernel at ~400GB/s.
// ---------------------------------------------------------------------------
__device__ __forceinline__ void gemm_tile(const float* __restrict__ A, int lda,
                                          const float* __restrict__ Bn, int ldb,
                                          int k0, int ntiles,
                                          float* __restrict__ dst, int ldd) {
    __shared__ __align__(16) float As[32][68];
    __shared__ __align__(16) float Bs[32][68];
    int t = threadIdx.x, lane = t & 31, wid = t >> 5;
    float acc[8];
    #pragma unroll
    for (int j = 0; j < 8; j++) acc[j] = 0.f;

    for (int kt = 0; kt < ntiles; kt++) {
        int kk0 = k0 + kt * 64;
        #pragma unroll
        for (int i = 0; i < 4; i++) {
            int idx = t + i * 128;              // 512 float4 each
            int r = idx >> 4, c = (idx & 15) * 4;
            *(float4*)&As[r][c] = *(const float4*)&A [(size_t)r * lda + kk0 + c];
            *(float4*)&Bs[r][c] = *(const float4*)&Bn[(size_t)r * ldb + kk0 + c];
        }
        __syncthreads();
        #pragma unroll
        for (int i = 0; i < 16; i++) {
            float4 b = *(const float4*)&Bs[lane][i * 4];
            #pragma unroll
            for (int j = 0; j < 8; j++) {
                float4 a = *(const float4*)&As[wid * 8 + j][i * 4];
                acc[j] += a.x*b.x + a.y*b.y + a.z*b.z + a.w*b.w;
            }
        }
        __syncthreads();
    }
    #pragma unroll
    for (int j = 0; j < 8; j++)
        dst[(size_t)(wid * 8 + j) * ldd + lane] = acc[j];   // coalesced
}

// ---------------------------------------------------------------------------
// K1 front:
//  [0,160):   proj GEMM (40 n-groups x 4 K-splits, 4 tiles each) -> g_qp[ks]
//  [160,672): src-half of output GEMM (32 n-groups x 16 K-splits) -> g_hs[ks]
//  [672,674): mask dtype detection + g_cnt reset
// ---------------------------------------------------------------------------
__global__ void k_front(const float* __restrict__ src,
                        const float* __restrict__ Wu,
                        const float* __restrict__ Wc,
                        const float* __restrict__ Wo,
                        const unsigned int* __restrict__ llm,
                        const unsigned int* __restrict__ hlm) {
    int bx = blockIdx.x, t = threadIdx.x;
    if (bx >= 672) {
        if (bx == 672 && t < 32) g_cnt[t] = 0;   // counters for k_gemm_c epilogue
        // int32 words are {0,1}; f32 words are {0,0x3F800000}; packed uint8
        // words hit neither set (random 0/1 data).
        __shared__ int s_ni, s_nf;
        if (t == 0) { s_ni = 0; s_nf = 0; }
        __syncthreads();
        int which = bx - 672;
        const unsigned int* p = which ? hlm : llm;
        int n = which ? (B_*C_ / 4) : (NENT_*B_*ENT_ / 4);
        int ni = 0, nf = 0;
        for (int i = t; i < n; i += blockDim.x) {
            unsigned int w = p[i];
            if (w > 1u) ni = 1;
            if (w != 0u && w != 0x3F800000u) nf = 1;
        }
        if (ni) atomicOr(&s_ni, 1);
        if (nf) atomicOr(&s_nf, 1);
        __syncthreads();
        if (t == 0) {
            int mode = (!s_ni) ? 0 : ((!s_nf) ? 1 : 2);
            if (which) g_mode_hl = mode; else g_mode_ll = mode;
        }
        return;
    }
    if (bx < 160) {
        int g = bx >> 2, ks = bx & 3;
        int n0 = g * 32;
        const float* Bn;
        if (n0 < 256) Bn = Wu + (size_t)n0 * D_;
        else          Bn = Wc + (size_t)(n0 - 256) * D_;
        gemm_tile(src, D_, Bn, D_, ks * 256, 4, &g_qp[ks][n0], UD_ + D_);
    } else {
        int h = bx - 160;
        int g = h >> 4, ks = h & 15;          // 32 n-groups x 16 K-splits
        int n0 = g * 32;
        gemm_tile(src, D_, Wo + (size_t)n0 * (2*D_) + D_, 2*D_,
                  ks * 64, 1, &g_hs[ks][n0], D_);
    }
}

// ---------------------------------------------------------------------------
// K2 align (128 threads):
//  [0,2048): unit blocks (e,b). Ballot-COMPACT unmasked rows, warp w takes
//            compacted positions [w*8, w*8+8) in two batches of 4 rows
//            (= 8 independent LDG.128 in flight, no predicated loads).
//            Block-local per-entity masked softmax; writes au.
//            First 256 blocks also zero g_c for K3's atomics.
//  [2048,2080): chunk blocks (one per b): 65 chunk dots + softmax -> ac.
// ---------------------------------------------------------------------------
__global__ void k_align(const float* __restrict__ pe,
                        const float* __restrict__ hl,
                        const void* llm, const void* hlm,
                        float* __restrict__ out) {
    int t = threadIdx.x, w = t >> 5, lane = t & 31;
    if (blockIdx.x < 2048) {
        int b = blockIdx.x & 31, e = blockIdx.x >> 5;
        if (blockIdx.x < 256 && t < 32)
            ((float4*)g_c)[blockIdx.x * 32 + t] = make_float4(0.f, 0.f, 0.f, 0.f);
        __shared__ __align__(16) float sq[UD_];
        __shared__ float s_val[ENT_];
        __shared__ int   sidx[ENT_];
        __shared__ int   scnt;
        if (t < 64) {
            float4 q = make_float4(0.f, 0.f, 0.f, 0.f);
            #pragma unroll
            for (int ks = 0; ks < KSPL; ks++) {
                float4 p = ((const float4*)g_qp[ks])[b * ((UD_+D_)/4) + t];
                q.x += p.x; q.y += p.y; q.z += p.z; q.w += p.w;
            }
            ((float4*)sq)[t] = q;
        }
        if (t >= 64 && t < 96) s_val[t - 64] = -INFINITY;
        if (w == 0) {
            bool ok = !read_mask(llm, e * (B_*ENT_) + b * ENT_ + lane, g_mode_ll);
            unsigned bm = __ballot_sync(0xFFFFFFFFu, ok);
            int pos = __popc(bm & ((1u << lane) - 1u));
            if (ok) sidx[pos] = lane;
            if (lane == 0) scnt = __popc(bm);
        }
        __syncthreads();
        int cnt = scnt;
        float4 q0 = ((const float4*)sq)[lane];
        float4 q1 = ((const float4*)sq)[lane + 32];
        const float4* peb = (const float4*)pe + (size_t)b * (UD_/4) + lane;
        const size_t RS = (size_t)B_ * UD_ / 4;
        #pragma unroll
        for (int half = 0; half < 2; half++) {
            int p0 = w * 8 + half * 4;
            int rows[4];
            float4 v[4][2];
            #pragma unroll
            for (int r = 0; r < 4; r++) {
                int p = p0 + r;
                if (p < cnt) {
                    int row = sidx[p];
                    rows[r] = row;
                    const float4* pp = peb + (size_t)(e * ENT_ + row) * RS;
                    v[r][0] = pp[0];
                    v[r][1] = pp[32];
                } else rows[r] = -1;
            }
            #pragma unroll
            for (int r = 0; r < 4; r++) {
                if (rows[r] >= 0) {
                    float acc = v[r][0].x*q0.x + v[r][0].y*q0.y + v[r][0].z*q0.z + v[r][0].w*q0.w
                              + v[r][1].x*q1.x + v[r][1].y*q1.y + v[r][1].z*q1.z + v[r][1].w*q1.w;
                    acc = warp_sum(acc);
                    if (lane == 0) s_val[rows[r]] = acc;
                }
            }
        }
        __syncthreads();
        if (w == 0) {
            float vv = s_val[lane];
            float mx = warp_max(vv);
            float au;
            if (mx == -INFINITY) {
                au = 0.f;                       // all-masked entity
            } else {
                float ex = (vv == -INFINITY) ? 0.f : __expf(vv - mx);
                float sm = warp_sum(ex);
                au = ex / sm;
            }
            out[OUT_AU + b * S_ + e * ENT_ + lane] = au;
        }
    } else {
        int b = blockIdx.x - 2048;
        __shared__ __align__(16) float sqc[D_];
        __shared__ float s_sc[C_];
        #pragma unroll
        for (int h = 0; h < 2; h++) {
            float4 q = make_float4(0.f, 0.f, 0.f, 0.f);
            #pragma unroll
            for (int ks = 0; ks < KSPL; ks++) {
                float4 p = ((const float4*)g_qp[ks])[b * ((UD_+D_)/4) + 64 + t + h*128];
                q.x += p.x; q.y += p.y; q.z += p.z; q.w += p.w;
            }
            ((float4*)sqc)[t + h*128] = q;
        }
        __syncthreads();
        int mhl = g_mode_hl;
        for (int c = w; c < C_; c += 4) {
            if (read_mask(hlm, b * C_ + c, mhl)) {
                if (lane == 0) s_sc[c] = -INFINITY;
                continue;
            }
            const float4* p = (const float4*)hl + ((size_t)c * B_ + b) * (D_/4);
            float acc = 0.f;
            #pragma unroll
            for (int it = 0; it < 8; it++) {
                float4 x = p[lane + it*32];
                float4 y = ((const float4*)sqc)[lane + it*32];
                acc += x.x*y.x + x.y*y.y + x.z*y.z + x.w*y.w;
            }
            acc = warp_sum(acc);
            if (lane == 0) s_sc[c] = acc;
        }
        __syncthreads();
        if (t == 0) {
            float mx = -INFINITY;
            for (int c = 0; c < C_; c++) mx = fmaxf(mx, s_sc[c]);
            float sum = 0.f;
            for (int c = 0; c < C_; c++) {
                float e = (s_sc[c] == -INFINITY) ? 0.f : __expf(s_sc[c] - mx);
                s_sc[c] = e; sum += e;
            }
            float inv = 1.f / sum;
            for (int c = 1; c < C_; c++) {
                float vv = s_sc[c] * inv;
                g_acs[b * NENT_ + (c-1)] = vv;
                out[OUT_AC + b * (C_-1) + (c-1)] = vv;
            }
        }
    }
}

// ---------------------------------------------------------------------------
// K3 context (unchanged — measured near its scattered-row floor).
// Block = (e,b,half); av = au*ac[e], ballot-compacted weights, up to 16
// LDG.128 in flight, RED.ADD.F32 into g_c. ~75% of rows never loaded.
// ---------------------------------------------------------------------------
__global__ void k_context(const float* __restrict__ ll, float* __restrict__ out) {
    int e = blockIdx.x, b = blockIdx.y, half = blockIdx.z, t = threadIdx.x;
    __shared__ float sw[ENT_];
    __shared__ int   sidx[ENT_];
    __shared__ int   scnt;
    float ac = g_acs[b * NENT_ + e];
    if (t < 32) {
        float au = out[OUT_AU + b * S_ + e * ENT_ + t];
        float av = au * ac;
        if (half == 0) out[OUT_AV + b * S_ + e * ENT_ + t] = av;
        unsigned m = __ballot_sync(0xFFFFFFFFu, av != 0.f);
        int pos = __popc(m & ((1u << t) - 1u));
        if (av != 0.f) { sw[pos] = av; sidx[pos] = t; }
        if (t == 0) scnt = __popc(m);
    }
    __syncthreads();
    int cnt = scnt;
    if (cnt == 0) return;
    float4 acc = make_float4(0.f, 0.f, 0.f, 0.f);
    const float4* base = (const float4*)ll + (size_t)b * (D_/4) + half * 128 + t;
    const size_t RS = (size_t)B_ * D_ / 4;
    int k = 0;
    for (; k + 16 <= cnt; k += 16) {
        float4 v[16];
        #pragma unroll
        for (int u = 0; u < 16; u++)
            v[u] = base[(size_t)(e * ENT_ + sidx[k + u]) * RS];
        #pragma unroll
        for (int u = 0; u < 16; u++) {
            float w = sw[k + u];
            acc.x += w * v[u].x; acc.y += w * v[u].y;
            acc.z += w * v[u].z; acc.w += w * v[u].w;
        }
    }
    for (; k + 8 <= cnt; k += 8) {
        float4 v[8];
        #pragma unroll
        for (int u = 0; u < 8; u++)
            v[u] = base[(size_t)(e * ENT_ + sidx[k + u]) * RS];
        #pragma unroll
        for (int u = 0; u < 8; u++) {
            float w = sw[k + u];
            acc.x += w * v[u].x; acc.y += w * v[u].y;
            acc.z += w * v[u].z; acc.w += w * v[u].w;
        }
    }
    for (; k + 4 <= cnt; k += 4) {
        float4 v[4];
        #pragma unroll
        for (int u = 0; u < 4; u++)
            v[u] = base[(size_t)(e * ENT_ + sidx[k + u]) * RS];
        #pragma unroll
        for (int u = 0; u < 4; u++) {
            float w = sw[k + u];
            acc.x += w * v[u].x; acc.y += w * v[u].y;
            acc.z += w * v[u].z; acc.w += w * v[u].w;
        }
    }
    for (; k < cnt; k++) {
        float4 v = base[(size_t)(e * ENT_ + sidx[k]) * RS];
        float w = sw[k];
        acc.x += w * v.x; acc.y += w * v.y; acc.z += w * v.z; acc.w += w * v.w;
    }
    float* dst = &g_c[b * D_ + half * 512 + t * 4];
    atomicAdd(dst + 0, acc.x);
    atomicAdd(dst + 1, acc.y);
    atomicAdd(dst + 2, acc.z);
    atomicAdd(dst + 3, acc.w);
}

// ---------------------------------------------------------------------------
// K4: c-half of the output GEMM + FUSED tanh epilogue.
// 32 n-groups x 16 K-splits = 512 single-tile blocks. The last block of each
// n-group (atomic counter) sums the 16 hc + 16 hs partials for its 32x32
// output tile and writes tanh — no separate k_tanh launch. hc partials are
// read with __ldcg (L2) after __threadfence for cross-block visibility.
// ---------------------------------------------------------------------------
__global__ void k_gemm_c(const float* __restrict__ Wo, float* __restrict__ out) {
    int g = blockIdx.x >> 4, ks = blockIdx.x & 15;
    int n0 = g * 32;
    int t = threadIdx.x;
    gemm_tile(g_c, D_, Wo + (size_t)n0 * (2*D_), 2*D_,
              ks * 64, 1, &g_hc[ks][n0], D_);

    __threadfence();
    __shared__ int s_last;
    if (t == 0) s_last = (atomicAdd(&g_cnt[g], 1) == KSW - 1);
    __syncthreads();
    if (!s_last) return;

    #pragma unroll
    for (int i = 0; i < 2; i++) {
        int id = t + i * 128;                 // 256 float4 = 32 rows x 8
        int m = id >> 3, c4 = id & 7;
        int idx = m * (D_/4) + (n0 >> 2) + c4;
        float4 s = make_float4(0.f, 0.f, 0.f, 0.f);
        #pragma unroll
        for (int k = 0; k < KSW; k++) {
            float4 a = __ldcg((const float4*)g_hc[k] + idx);
            float4 b = ((const float4*)g_hs[k])[idx];
            s.x += a.x + b.x; s.y += a.y + b.y;
            s.z += a.z + b.z; s.w += a.w + b.w;
        }
        float4 r;
        r.x = tanhf(s.x); r.y = tanhf(s.y); r.z = tanhf(s.z); r.w = tanhf(s.w);
        *(float4*)&out[OUT_ATTN + m * D_ + n0 + c4 * 4] = r;
    }
}

// ---------------------------------------------------------------------------
extern "C" void kernel_launch(void* const* d_in, const int* in_sizes, int n_in,
                              void* d_out, int out_size) {
    const float* src = (const float*)d_in[0];
    const float* hl  = (const float*)d_in[1];
    const float* pe  = (const float*)d_in[2];
    const float* ll  = (const float*)d_in[3];
    const void*  llm = d_in[4];
    const void*  hlm = d_in[5];
    const float* Wu  = (const float*)d_in[6];
    const float* Wc  = (const float*)d_in[7];
    const float* Wo  = (const float*)d_in[8];
    float* out = (float*)d_out;

    k_front<<<674, 128>>>(src, Wu, Wc, Wo,
                          (const unsigned int*)llm, (const unsigned int*)hlm);
    k_align<<<2048 + 32, 128>>>(pe, hl, llm, hlm, out);
    k_context<<<dim3(NENT_, B_, 2), 128>>>(ll, out);
    k_gemm_c<<<512, 128>>>(Wo, out);
}